// round 12
// baseline (speedup 1.0000x reference)
#include <cuda_runtime.h>
#include <cstdint>

#define NFULL 0xffffffffu

namespace {
constexpr int BB   = 8;
constexpr int SS   = 4096;
constexpr int DM   = 256;
constexpr int DI   = 512;
constexpr int DS   = 16;
constexpr int MT   = BB * SS;   // 32768 tokens
constexpr int NCH  = 64;        // scan chunks
constexpr int CL   = SS / NCH;  // 64 steps per chunk
constexpr float EPSV = 1e-5f;
}

// ------------------------------------------------------------------ scratch
__device__ __align__(16) float g_x    [MT * DM];   // residual stream
__device__ __align__(16) float g_xn   [MT * DM];   // layernorm output
__device__ __align__(16) float g_xp   [MT * DI];   // inproj half 1
__device__ __align__(16) float g_z    [MT * DI];   // inproj half 2 (gate)
__device__ __align__(16) float g_xc   [MT * DI];   // conv+silu output
__device__ __align__(16) float g_y    [MT * DI];   // scan output (gated by scan3)
__device__ __align__(16) float g_Bm   [MT * DS];
__device__ __align__(16) float g_Cm   [MT * DS];
__device__ __align__(16) float g_dtraw[MT];
__device__ __align__(16) float g_cumf [BB * NCH * DI];       // chunk-final cumsum
__device__ __align__(16) float g_hf   [BB * NCH * DS * DI];
__device__ __align__(16) float g_h0   [BB * NCH * DS * DI];

__device__ __forceinline__ float siluf(float x) {
    return x / (1.f + __expf(-x));
}

// ----------------------------------------- fused inproj + layernorm (layer 0)
__global__ void k_inln(const float* __restrict__ z,
                       const float* __restrict__ w,
                       const float* __restrict__ ipb,
                       const float* __restrict__ g,
                       const float* __restrict__ b) {
    int warp = (blockIdx.x * blockDim.x + threadIdx.x) >> 5;
    int lane = threadIdx.x & 31;
    if (warp >= MT) return;
    float4 zv = *reinterpret_cast<const float4*>(z + (size_t)warp * 4);
    float v[8];
    float s = 0.f;
#pragma unroll
    for (int i = 0; i < 8; i++) {
        int c = i * 32 + lane;
        float4 wv = *reinterpret_cast<const float4*>(w + (size_t)c * 4);
        v[i] = ipb[c] + zv.x * wv.x + zv.y * wv.y + zv.z * wv.z + zv.w * wv.w;
        g_x[(size_t)warp * DM + c] = v[i];
        s += v[i];
    }
#pragma unroll
    for (int o = 16; o; o >>= 1) s += __shfl_xor_sync(NFULL, s, o);
    float mu = s * (1.f / DM);
    float q = 0.f;
#pragma unroll
    for (int i = 0; i < 8; i++) { float d = v[i] - mu; q += d * d; }
#pragma unroll
    for (int o = 16; o; o >>= 1) q += __shfl_xor_sync(NFULL, q, o);
    float r = rsqrtf(q * (1.f / DM) + EPSV);
#pragma unroll
    for (int i = 0; i < 8; i++) {
        int c = i * 32 + lane;
        g_xn[(size_t)warp * DM + c] = (v[i] - mu) * r * g[c] + b[c];
    }
}

// ----------------------------------------------------------------- layernorm
__global__ void k_ln(const float* __restrict__ g, const float* __restrict__ b) {
    int warp = (blockIdx.x * blockDim.x + threadIdx.x) >> 5;
    int lane = threadIdx.x & 31;
    if (warp >= MT) return;
    const float* xr = g_x + (size_t)warp * DM;
    float v[8];
    float s = 0.f;
#pragma unroll
    for (int i = 0; i < 8; i++) { v[i] = xr[i * 32 + lane]; s += v[i]; }
#pragma unroll
    for (int o = 16; o; o >>= 1) s += __shfl_xor_sync(NFULL, s, o);
    float mu = s * (1.f / DM);
    float q = 0.f;
#pragma unroll
    for (int i = 0; i < 8; i++) { float d = v[i] - mu; q += d * d; }
#pragma unroll
    for (int o = 16; o; o >>= 1) q += __shfl_xor_sync(NFULL, q, o);
    float r = rsqrtf(q * (1.f / DM) + EPSV);
    float* out = g_xn + (size_t)warp * DM;
#pragma unroll
    for (int i = 0; i < 8; i++) {
        int c = i * 32 + lane;
        out[c] = (v[i] - mu) * r * g[c] + b[c];
    }
}

// ------------------------------------------------------------------- GEMM v5
// C(MT x N) = A(MT x K) * W^T. BK=16, 256 threads, double-buffered smem,
// one barrier per 16-k chunk, 2 CTAs/SM.
// MODE 0: tile 128x128, A=g_xn (K=256), N=1024 -> g_xp / g_z.
// MODE 1: tile 128x64, A=g_y (gated, K=512), N=256 -> g_x += (residual).
template <int MODE>
__global__ __launch_bounds__(256, 2)
void k_gemm(const float* __restrict__ W) {
    constexpr int K  = (MODE == 0) ? DM : DI;
    constexpr int TN = (MODE == 0) ? 128 : 64;
    constexpr int WN = TN / 2;
    constexpr int BK = 16;
    __shared__ float As[2][BK][128];
    __shared__ float Bs[2][BK][TN];
    const int tid = threadIdx.x;
    const int mBase = blockIdx.y * 128;
    const int nBase = blockIdx.x * TN;
    const int warp = tid >> 5, lane = tid & 31;
    const int wr = warp & 3;
    const int wc = warp >> 2;
    const int lr2 = lane >> 3;
    const int lcx = lane & 7;
    const int lr = tid >> 1;
    const int lc = (tid & 1) * 8;
    const int lrB = (MODE == 0) ? lr : (tid >> 2);
    const int lcB = (MODE == 0) ? lc : ((tid & 3) * 4);

    const float* Aptr = (MODE == 0) ? g_xn : g_y;
    const float* aRow = Aptr + (size_t)(mBase + lr) * K + lc;
    const float* bRow = W + (size_t)(nBase + lrB) * K + lcB;

    float4 pa0, pa1, pb0, pb1;
    auto loadAB = [&](int k0) {
        pa0 = *reinterpret_cast<const float4*>(aRow + k0);
        pa1 = *reinterpret_cast<const float4*>(aRow + k0 + 4);
        pb0 = *reinterpret_cast<const float4*>(bRow + k0);
        if (MODE == 0)
            pb1 = *reinterpret_cast<const float4*>(bRow + k0 + 4);
    };
    auto store = [&](int st) {
        As[st][lc + 0][lr] = pa0.x; As[st][lc + 1][lr] = pa0.y;
        As[st][lc + 2][lr] = pa0.z; As[st][lc + 3][lr] = pa0.w;
        As[st][lc + 4][lr] = pa1.x; As[st][lc + 5][lr] = pa1.y;
        As[st][lc + 6][lr] = pa1.z; As[st][lc + 7][lr] = pa1.w;
        Bs[st][lcB + 0][lrB] = pb0.x; Bs[st][lcB + 1][lrB] = pb0.y;
        Bs[st][lcB + 2][lrB] = pb0.z; Bs[st][lcB + 3][lrB] = pb0.w;
        if (MODE == 0) {
            Bs[st][lcB + 4][lrB] = pb1.x; Bs[st][lcB + 5][lrB] = pb1.y;
            Bs[st][lcB + 6][lrB] = pb1.z; Bs[st][lcB + 7][lrB] = pb1.w;
        }
    };

    constexpr int NJ = (MODE == 0) ? 8 : 4;
    float acc[8][NJ];
#pragma unroll
    for (int i = 0; i < 8; i++)
#pragma unroll
        for (int j = 0; j < NJ; j++) acc[i][j] = 0.f;

    loadAB(0);
    store(0);
    __syncthreads();

    const int aOff0 = wr * 32 + lr2 * 4;
    const int bOff0 = wc * WN + lcx * 4;

    for (int k0 = 0; k0 < K; k0 += BK) {
        const int cur = (k0 >> 4) & 1;
        const bool more = (k0 + BK) < K;
        if (more) loadAB(k0 + BK);
#pragma unroll
        for (int kk = 0; kk < BK; kk++) {
            float4 a0 = *reinterpret_cast<const float4*>(&As[cur][kk][aOff0]);
            float4 a1 = *reinterpret_cast<const float4*>(&As[cur][kk][aOff0 + 16]);
            const float af[8] = {a0.x, a0.y, a0.z, a0.w, a1.x, a1.y, a1.z, a1.w};
            float bf[NJ];
            {
                float4 b0 = *reinterpret_cast<const float4*>(&Bs[cur][kk][bOff0]);
                bf[0] = b0.x; bf[1] = b0.y; bf[2] = b0.z; bf[3] = b0.w;
                if (MODE == 0) {
                    float4 b1 = *reinterpret_cast<const float4*>(&Bs[cur][kk][bOff0 + 32]);
                    bf[4] = b1.x; bf[5] = b1.y; bf[6] = b1.z; bf[7] = b1.w;
                }
            }
#pragma unroll
            for (int i = 0; i < 8; i++)
#pragma unroll
                for (int j = 0; j < NJ; j++)
                    acc[i][j] = fmaf(af[i], bf[j], acc[i][j]);
        }
        if (more) store(cur ^ 1);
        __syncthreads();
    }

#pragma unroll
    for (int i = 0; i < 8; i++) {
        int row = mBase + wr * 32 + (i >> 2) * 16 + lr2 * 4 + (i & 3);
#pragma unroll
        for (int jh = 0; jh < NJ / 4; jh++) {
            int n0 = nBase + wc * WN + jh * 32 + lcx * 4;
            float4 v = make_float4(acc[i][jh * 4], acc[i][jh * 4 + 1],
                                   acc[i][jh * 4 + 2], acc[i][jh * 4 + 3]);
            if (MODE == 0) {
                float* dst = (n0 < DI) ? (g_xp + (size_t)row * DI + n0)
                                       : (g_z  + (size_t)row * DI + n0 - DI);
                *reinterpret_cast<float4*>(dst) = v;
            } else {
                float4* p = reinterpret_cast<float4*>(g_x + (size_t)row * DM + n0);
                float4 o = *p;
                o.x += v.x; o.y += v.y; o.z += v.z; o.w += v.w;
                *p = o;
            }
        }
    }
}

// ---------------------------------- fused depthwise conv + SiLU + xproj GEMV
// v3: Wx staged in smem in 8-row groups (LDS stride-32, conflict-free).
// 512 threads = 16 tokens/CTA amortizes staging.
__global__ __launch_bounds__(512)
void k_cxp(const float* __restrict__ cw, const float* __restrict__ cb,
           const float* __restrict__ Wx) {
    __shared__ float sW[8][512];   // 16 KB
    const int tid = threadIdx.x;
    const int warp = blockIdx.x * 16 + (tid >> 5);   // global token
    const int lane = tid & 31;
    const int t = warp & (SS - 1);

    float v[16];
#pragma unroll
    for (int i = 0; i < 16; i++) {
        int d = i * 32 + lane;
        float acc = cb[d];
        float4 wv = *reinterpret_cast<const float4*>(cw + (size_t)d * 4);
#pragma unroll
        for (int j = 0; j < 4; j++) {
            int tt = t - 3 + j;
            if (tt >= 0)
                acc = fmaf(g_xp[(size_t)(warp + j - 3) * DI + d], (&wv.x)[j], acc);
        }
        v[i] = siluf(acc);
        g_xc[(size_t)warp * DI + d] = v[i];
    }

#pragma unroll
    for (int ng = 0; ng < 5; ng++) {
        const int n0 = ng * 8;
        const int cnt = (ng == 4) ? 1 : 8;
        __syncthreads();
        for (int idx = tid; idx < cnt * 128; idx += 512) {
            int r = idx >> 7, c4 = idx & 127;
            reinterpret_cast<float4*>(sW[r])[c4] =
                reinterpret_cast<const float4*>(Wx + (size_t)(n0 + r) * DI)[c4];
        }
        __syncthreads();
#pragma unroll
        for (int nn = 0; nn < 8; nn++) {
            if (nn >= cnt) break;
            const int n = n0 + nn;
            float acc = 0.f;
#pragma unroll
            for (int i = 0; i < 16; i++)
                acc = fmaf(v[i], sW[nn][i * 32 + lane], acc);
#pragma unroll
            for (int o = 16; o; o >>= 1) acc += __shfl_xor_sync(NFULL, acc, o);
            if (lane == 0) {
                if (n < DS)          g_Bm[(size_t)warp * DS + n] = acc;
                else if (n < 2 * DS) g_Cm[(size_t)warp * DS + n - DS] = acc;
                else                 g_dtraw[warp] = acc;
            }
        }
    }
}

// w^(s+1) powers via multiply tree
__device__ __forceinline__ void powers16(float w, float* p) {
    p[0] = w;
    p[1] = w * w;
    p[2] = p[1] * w;    p[3]  = p[1] * p[1];
    p[4] = p[3] * w;    p[5]  = p[3] * p[1];
    p[6] = p[3] * p[2]; p[7]  = p[3] * p[3];
    p[8] = p[7] * w;    p[9]  = p[7] * p[1];
    p[10] = p[7] * p[2]; p[11] = p[7] * p[3];
    p[12] = p[7] * p[4]; p[13] = p[7] * p[5];
    p[14] = p[7] * p[6]; p[15] = p[7] * p[7];
}

// ------------------------------------------- scan phase 1: per-chunk scan
__global__ __launch_bounds__(128)
void k_scan1(const float* __restrict__ dw, const float* __restrict__ db) {
    __shared__ float Bs[CL * DS], Cs[CL * DS], dts[CL];
    const int d = blockIdx.x * 128 + threadIdx.x;
    const int c = blockIdx.y, b = blockIdx.z;
    const int tid = threadIdx.x;
    const size_t baseT = (size_t)b * SS + c * CL;

    const float4* Bsrc = reinterpret_cast<const float4*>(g_Bm + baseT * DS);
    const float4* Csrc = reinterpret_cast<const float4*>(g_Cm + baseT * DS);
#pragma unroll
    for (int i = 0; i < CL * DS / 4 / 128; i++) {
        reinterpret_cast<float4*>(Bs)[tid + i * 128] = Bsrc[tid + i * 128];
        reinterpret_cast<float4*>(Cs)[tid + i * 128] = Csrc[tid + i * 128];
    }
    if (tid < CL / 4)
        reinterpret_cast<float4*>(dts)[tid] =
            reinterpret_cast<const float4*>(g_dtraw + baseT)[tid];
    __syncthreads();

    const float dwv = dw[d], dbv = db[d];
    float h[DS];
#pragma unroll
    for (int s = 0; s < DS; s++) h[s] = 0.f;
    float cum = 0.f;

    float xnext = g_xc[baseT * DI + d];
    for (int t = 0; t < CL; t++) {
        float x = xnext;
        if (t + 1 < CL) xnext = g_xc[(baseT + t + 1) * DI + d];
        float xr = dts[t] * dwv + dbv;
        xr = fminf(fmaxf(xr, -30.f), 30.f);
        float e = __expf(xr);
        float w = __frcp_rn(1.f + e);      // exp(-dt)
        float dtv = -__logf(w);            // softplus(xr)
        cum += dtv;
        float u = dtv * x;
        float p[DS];
        powers16(w, p);
        float y = 0.f;
#pragma unroll
        for (int s = 0; s < DS; s++) {
            h[s] = fmaf(h[s], p[s], u * Bs[t * DS + s]);
            y = fmaf(h[s], Cs[t * DS + s], y);
        }
        g_y[(baseT + t) * DI + d] = y;
    }
    g_cumf[((size_t)(b * NCH + c)) * DI + d] = cum;
#pragma unroll
    for (int s = 0; s < DS; s++)
        g_hf[((size_t)(b * NCH + c) * DS + s) * DI + d] = h[s];
}

// ------------------------------------------- scan phase 2: chain chunk states
__global__ void k_scan2() {
    int idx = blockIdx.x * blockDim.x + threadIdx.x;
    if (idx >= BB * DS * DI) return;
    const int d = idx % DI;
    const int s = (idx / DI) % DS;
    const int b = idx / (DI * DS);
    float h = 0.f;
    const float sf = (float)(s + 1);
    for (int c = 0; c < NCH; c++) {
        size_t o = ((size_t)(b * NCH + c) * DS + s) * DI + d;
        g_h0[o] = h;
        float cumt = g_cumf[((size_t)(b * NCH + c)) * DI + d];
        h = fmaf(__expf(-sf * cumt), h, g_hf[o]);
    }
}

// --------------------- scan phase 3: h0 correction + SiLU gating (in place)
__global__ __launch_bounds__(128)
void k_scan3(const float* __restrict__ dw, const float* __restrict__ db) {
    __shared__ float Cs[CL * DS], dts[CL];
    const int c = blockIdx.y;
    const int d = blockIdx.x * 128 + threadIdx.x;
    const int b = blockIdx.z;
    const int tid = threadIdx.x;
    const size_t baseT = (size_t)b * SS + c * CL;

    if (c > 0) {
        const float4* Csrc = reinterpret_cast<const float4*>(g_Cm + baseT * DS);
#pragma unroll
        for (int i = 0; i < CL * DS / 4 / 128; i++)
            reinterpret_cast<float4*>(Cs)[tid + i * 128] = Csrc[tid + i * 128];
        if (tid < CL / 4)
            reinterpret_cast<float4*>(dts)[tid] =
                reinterpret_cast<const float4*>(g_dtraw + baseT)[tid];
        __syncthreads();

        const float dwv = dw[d], dbv = db[d];
        float h0[DS];
#pragma unroll
        for (int s = 0; s < DS; s++)
            h0[s] = g_h0[((size_t)(b * NCH + c) * DS + s) * DI + d];

        float wcum = 1.f;
        for (int t = 0; t < CL; t++) {
            size_t idx = (baseT + t) * DI + d;
            float xr = dts[t] * dwv + dbv;
            xr = fminf(fmaxf(xr, -30.f), 30.f);
            float e = __expf(xr);
            wcum *= __frcp_rn(1.f + e);    // *= exp(-dt_t)
            float p[DS];
            powers16(wcum, p);
            float y = g_y[idx];
#pragma unroll
            for (int s = 0; s < DS; s++)
                y = fmaf(h0[s] * p[s], Cs[t * DS + s], y);
            g_y[idx] = y * siluf(g_z[idx]);
        }
    } else {
        for (int t = 0; t < CL; t++) {
            size_t idx = (baseT + t) * DI + d;
            g_y[idx] = g_y[idx] * siluf(g_z[idx]);
        }
    }
}

// ---------------------------------------------------------- final LN + head
__global__ void k_final(const float* __restrict__ g, const float* __restrict__ b,
                        const float* __restrict__ ow, const float* __restrict__ ob,
                        float* __restrict__ out) {
    int warp = (blockIdx.x * blockDim.x + threadIdx.x) >> 5;
    int lane = threadIdx.x & 31;
    if (warp >= MT) return;
    const float* xr = g_x + (size_t)warp * DM;
    float v[8];
    float s = 0.f;
#pragma unroll
    for (int i = 0; i < 8; i++) { v[i] = xr[i * 32 + lane]; s += v[i]; }
#pragma unroll
    for (int o = 16; o; o >>= 1) s += __shfl_xor_sync(NFULL, s, o);
    float mu = s * (1.f / DM);
    float q = 0.f;
#pragma unroll
    for (int i = 0; i < 8; i++) { float d = v[i] - mu; q += d * d; }
#pragma unroll
    for (int o = 16; o; o >>= 1) q += __shfl_xor_sync(NFULL, q, o);
    float r = rsqrtf(q * (1.f / DM) + EPSV);
    float a0 = 0.f, a1 = 0.f;
#pragma unroll
    for (int i = 0; i < 8; i++) {
        int c = i * 32 + lane;
        float xn = (v[i] - mu) * r * g[c] + b[c];
        a0 += xn * ow[c];
        a1 += xn * ow[DM + c];
    }
#pragma unroll
    for (int o = 16; o; o >>= 1) {
        a0 += __shfl_xor_sync(NFULL, a0, o);
        a1 += __shfl_xor_sync(NFULL, a1, o);
    }
    if (lane == 0) {
        out[(size_t)warp * 2 + 0] = a0 + ob[0];
        out[(size_t)warp * 2 + 1] = a1 + ob[1];
    }
}

// ---------------------------------------------------------------------------
extern "C" void kernel_launch(void* const* d_in, const int* in_sizes, int n_in,
                              void* d_out, int out_size) {
    (void)in_sizes; (void)n_in; (void)out_size;
    const float* z_seq     = (const float*)d_in[0];
    const float* ip_w      = (const float*)d_in[1];
    const float* ip_b      = (const float*)d_in[2];
    const float* norm_g    = (const float*)d_in[3];
    const float* norm_b    = (const float*)d_in[4];
    const float* inproj_w  = (const float*)d_in[5];
    const float* conv_w    = (const float*)d_in[6];
    const float* conv_b    = (const float*)d_in[7];
    const float* xproj_w   = (const float*)d_in[8];
    const float* dt_w      = (const float*)d_in[9];
    const float* dt_b      = (const float*)d_in[10];
    const float* outproj_w = (const float*)d_in[11];
    const float* onorm_g   = (const float*)d_in[12];
    const float* onorm_b   = (const float*)d_in[13];
    const float* op_w      = (const float*)d_in[14];
    const float* op_b      = (const float*)d_in[15];
    float* out = (float*)d_out;

    k_inln<<<MT / 8, 256>>>(z_seq, ip_w, ip_b, norm_g, norm_b);   // launch 1

    for (int l = 0; l < 2; l++) {
        if (l > 0)
            k_ln<<<MT / 8, 256>>>(norm_g + l * DM, norm_b + l * DM);
        k_gemm<0><<<dim3(2 * DI / 128, MT / 128), 256>>>(         // l=0: launch 2
            inproj_w + (size_t)l * 2 * DI * DM);
        k_cxp<<<MT / 16, 512>>>(conv_w + (size_t)l * DI * 4,      // l=0: launch 3
                                conv_b + (size_t)l * DI,
                                xproj_w + (size_t)l * (2 * DS + 1) * DI);
        k_scan1<<<dim3(DI / 128, NCH, BB), 128>>>(dt_w + (size_t)l * DI,  // l=0: launch 4
                                                  dt_b + (size_t)l * DI);
        k_scan2<<<BB * DS * DI / 256, 256>>>();
        k_scan3<<<dim3(DI / 128, NCH, BB), 128>>>(dt_w + (size_t)l * DI,
                                                  dt_b + (size_t)l * DI);
        k_gemm<1><<<dim3(DM / 64, MT / 128), 256>>>(
            outproj_w + (size_t)l * DM * DI);
    }

    k_final<<<MT / 8, 256>>>(onorm_g, onorm_b, op_w, op_b, out);
}

// round 13
// speedup vs baseline: 1.0569x; 1.0569x over previous
#include <cuda_runtime.h>
#include <cstdint>

#define NFULL 0xffffffffu

namespace {
constexpr int BB   = 8;
constexpr int SS   = 4096;
constexpr int DM   = 256;
constexpr int DI   = 512;
constexpr int DS   = 16;
constexpr int MT   = BB * SS;   // 32768 tokens
constexpr int NCH  = 64;        // scan chunks
constexpr int CL   = SS / NCH;  // 64 steps per chunk
constexpr float EPSV = 1e-5f;
}

// ------------------------------------------------------------------ scratch
__device__ __align__(16) float g_x    [MT * DM];   // residual stream
__device__ __align__(16) float g_xn   [MT * DM];   // layernorm output
__device__ __align__(16) float g_xp   [MT * DI];   // inproj half 1
__device__ __align__(16) float g_z    [MT * DI];   // inproj half 2 (gate)
__device__ __align__(16) float g_xc   [MT * DI];   // conv+silu output
__device__ __align__(16) float g_y    [MT * DI];   // scan output (gated by scan3)
__device__ __align__(16) float g_Bm   [MT * DS];
__device__ __align__(16) float g_Cm   [MT * DS];
__device__ __align__(16) float g_dtraw[MT];
__device__ __align__(16) float g_cumf [BB * NCH * DI];       // chunk-final cumsum
__device__ __align__(16) float g_hf   [BB * NCH * DS * DI];
__device__ __align__(16) float g_h0   [BB * NCH * DS * DI];

__device__ __forceinline__ float siluf(float x) {
    return x / (1.f + __expf(-x));
}

// ----------------------------------------- fused inproj + layernorm (layer 0)
__global__ void k_inln(const float* __restrict__ z,
                       const float* __restrict__ w,
                       const float* __restrict__ ipb,
                       const float* __restrict__ g,
                       const float* __restrict__ b) {
    int warp = (blockIdx.x * blockDim.x + threadIdx.x) >> 5;
    int lane = threadIdx.x & 31;
    if (warp >= MT) return;
    float4 zv = *reinterpret_cast<const float4*>(z + (size_t)warp * 4);
    float v[8];
    float s = 0.f;
#pragma unroll
    for (int i = 0; i < 8; i++) {
        int c = i * 32 + lane;
        float4 wv = *reinterpret_cast<const float4*>(w + (size_t)c * 4);
        v[i] = ipb[c] + zv.x * wv.x + zv.y * wv.y + zv.z * wv.z + zv.w * wv.w;
        g_x[(size_t)warp * DM + c] = v[i];
        s += v[i];
    }
#pragma unroll
    for (int o = 16; o; o >>= 1) s += __shfl_xor_sync(NFULL, s, o);
    float mu = s * (1.f / DM);
    float q = 0.f;
#pragma unroll
    for (int i = 0; i < 8; i++) { float d = v[i] - mu; q += d * d; }
#pragma unroll
    for (int o = 16; o; o >>= 1) q += __shfl_xor_sync(NFULL, q, o);
    float r = rsqrtf(q * (1.f / DM) + EPSV);
#pragma unroll
    for (int i = 0; i < 8; i++) {
        int c = i * 32 + lane;
        g_xn[(size_t)warp * DM + c] = (v[i] - mu) * r * g[c] + b[c];
    }
}

// ----------------------------------------------------------------- layernorm
__global__ void k_ln(const float* __restrict__ g, const float* __restrict__ b) {
    int warp = (blockIdx.x * blockDim.x + threadIdx.x) >> 5;
    int lane = threadIdx.x & 31;
    if (warp >= MT) return;
    const float* xr = g_x + (size_t)warp * DM;
    float v[8];
    float s = 0.f;
#pragma unroll
    for (int i = 0; i < 8; i++) { v[i] = xr[i * 32 + lane]; s += v[i]; }
#pragma unroll
    for (int o = 16; o; o >>= 1) s += __shfl_xor_sync(NFULL, s, o);
    float mu = s * (1.f / DM);
    float q = 0.f;
#pragma unroll
    for (int i = 0; i < 8; i++) { float d = v[i] - mu; q += d * d; }
#pragma unroll
    for (int o = 16; o; o >>= 1) q += __shfl_xor_sync(NFULL, q, o);
    float r = rsqrtf(q * (1.f / DM) + EPSV);
    float* out = g_xn + (size_t)warp * DM;
#pragma unroll
    for (int i = 0; i < 8; i++) {
        int c = i * 32 + lane;
        out[c] = (v[i] - mu) * r * g[c] + b[c];
    }
}

// ------------------------------------------------------------------- GEMM v5
// C(MT x N) = A(MT x K) * W^T. BK=16, 256 threads, double-buffered smem,
// one barrier per 16-k chunk, 2 CTAs/SM.
// MODE 0: tile 128x128, A=g_xn (K=256), N=1024 -> g_xp / g_z.
// MODE 1: tile 128x64, A=g_y (gated, K=512), N=256 -> g_x += (residual).
template <int MODE>
__global__ __launch_bounds__(256, 2)
void k_gemm(const float* __restrict__ W) {
    constexpr int K  = (MODE == 0) ? DM : DI;
    constexpr int TN = (MODE == 0) ? 128 : 64;
    constexpr int WN = TN / 2;
    constexpr int BK = 16;
    __shared__ float As[2][BK][128];
    __shared__ float Bs[2][BK][TN];
    const int tid = threadIdx.x;
    const int mBase = blockIdx.y * 128;
    const int nBase = blockIdx.x * TN;
    const int warp = tid >> 5, lane = tid & 31;
    const int wr = warp & 3;
    const int wc = warp >> 2;
    const int lr2 = lane >> 3;
    const int lcx = lane & 7;
    const int lr = tid >> 1;
    const int lc = (tid & 1) * 8;
    const int lrB = (MODE == 0) ? lr : (tid >> 2);
    const int lcB = (MODE == 0) ? lc : ((tid & 3) * 4);

    const float* Aptr = (MODE == 0) ? g_xn : g_y;
    const float* aRow = Aptr + (size_t)(mBase + lr) * K + lc;
    const float* bRow = W + (size_t)(nBase + lrB) * K + lcB;

    float4 pa0, pa1, pb0, pb1;
    auto loadAB = [&](int k0) {
        pa0 = *reinterpret_cast<const float4*>(aRow + k0);
        pa1 = *reinterpret_cast<const float4*>(aRow + k0 + 4);
        pb0 = *reinterpret_cast<const float4*>(bRow + k0);
        if (MODE == 0)
            pb1 = *reinterpret_cast<const float4*>(bRow + k0 + 4);
    };
    auto store = [&](int st) {
        As[st][lc + 0][lr] = pa0.x; As[st][lc + 1][lr] = pa0.y;
        As[st][lc + 2][lr] = pa0.z; As[st][lc + 3][lr] = pa0.w;
        As[st][lc + 4][lr] = pa1.x; As[st][lc + 5][lr] = pa1.y;
        As[st][lc + 6][lr] = pa1.z; As[st][lc + 7][lr] = pa1.w;
        Bs[st][lcB + 0][lrB] = pb0.x; Bs[st][lcB + 1][lrB] = pb0.y;
        Bs[st][lcB + 2][lrB] = pb0.z; Bs[st][lcB + 3][lrB] = pb0.w;
        if (MODE == 0) {
            Bs[st][lcB + 4][lrB] = pb1.x; Bs[st][lcB + 5][lrB] = pb1.y;
            Bs[st][lcB + 6][lrB] = pb1.z; Bs[st][lcB + 7][lrB] = pb1.w;
        }
    };

    constexpr int NJ = (MODE == 0) ? 8 : 4;
    float acc[8][NJ];
#pragma unroll
    for (int i = 0; i < 8; i++)
#pragma unroll
        for (int j = 0; j < NJ; j++) acc[i][j] = 0.f;

    loadAB(0);
    store(0);
    __syncthreads();

    const int aOff0 = wr * 32 + lr2 * 4;
    const int bOff0 = wc * WN + lcx * 4;

    for (int k0 = 0; k0 < K; k0 += BK) {
        const int cur = (k0 >> 4) & 1;
        const bool more = (k0 + BK) < K;
        if (more) loadAB(k0 + BK);
#pragma unroll
        for (int kk = 0; kk < BK; kk++) {
            float4 a0 = *reinterpret_cast<const float4*>(&As[cur][kk][aOff0]);
            float4 a1 = *reinterpret_cast<const float4*>(&As[cur][kk][aOff0 + 16]);
            const float af[8] = {a0.x, a0.y, a0.z, a0.w, a1.x, a1.y, a1.z, a1.w};
            float bf[NJ];
            {
                float4 b0 = *reinterpret_cast<const float4*>(&Bs[cur][kk][bOff0]);
                bf[0] = b0.x; bf[1] = b0.y; bf[2] = b0.z; bf[3] = b0.w;
                if (MODE == 0) {
                    float4 b1 = *reinterpret_cast<const float4*>(&Bs[cur][kk][bOff0 + 32]);
                    bf[4] = b1.x; bf[5] = b1.y; bf[6] = b1.z; bf[7] = b1.w;
                }
            }
#pragma unroll
            for (int i = 0; i < 8; i++)
#pragma unroll
                for (int j = 0; j < NJ; j++)
                    acc[i][j] = fmaf(af[i], bf[j], acc[i][j]);
        }
        if (more) store(cur ^ 1);
        __syncthreads();
    }

#pragma unroll
    for (int i = 0; i < 8; i++) {
        int row = mBase + wr * 32 + (i >> 2) * 16 + lr2 * 4 + (i & 3);
#pragma unroll
        for (int jh = 0; jh < NJ / 4; jh++) {
            int n0 = nBase + wc * WN + jh * 32 + lcx * 4;
            float4 v = make_float4(acc[i][jh * 4], acc[i][jh * 4 + 1],
                                   acc[i][jh * 4 + 2], acc[i][jh * 4 + 3]);
            if (MODE == 0) {
                float* dst = (n0 < DI) ? (g_xp + (size_t)row * DI + n0)
                                       : (g_z  + (size_t)row * DI + n0 - DI);
                *reinterpret_cast<float4*>(dst) = v;
            } else {
                float4* p = reinterpret_cast<float4*>(g_x + (size_t)row * DM + n0);
                float4 o = *p;
                o.x += v.x; o.y += v.y; o.z += v.z; o.w += v.w;
                *p = o;
            }
        }
    }
}

// ---------------------------------- fused depthwise conv + SiLU + xproj GEMV
// v4: one warp handles 4 consecutive tokens. Wx loads shared 4x; conv loads
// 7 overlapping xp rows instead of 4x4. Same v1 access pattern (d=i*32+lane).
__global__ __launch_bounds__(256)
void k_cxp(const float* __restrict__ cw, const float* __restrict__ cb,
           const float* __restrict__ Wx) {
    const int wid = (blockIdx.x * blockDim.x + threadIdx.x) >> 5;
    const int lane = threadIdx.x & 31;
    const int t0 = wid * 4;                 // first of 4 tokens
    if (t0 >= MT) return;
    const int tl0 = t0 & (SS - 1);          // local position in sequence

    float v[4][16];
#pragma unroll
    for (int i = 0; i < 16; i++) {
        const int d = i * 32 + lane;
        float4 wv = *reinterpret_cast<const float4*>(cw + (size_t)d * 4);
        const float cbv = cb[d];
        float xr[7];
#pragma unroll
        for (int k = 0; k < 7; k++) {
            int tt = tl0 - 3 + k;
            xr[k] = (tt >= 0) ? g_xp[(size_t)(t0 - 3 + k) * DI + d] : 0.f;
        }
#pragma unroll
        for (int tok = 0; tok < 4; tok++) {
            float acc = cbv;
            acc = fmaf(xr[tok + 0], wv.x, acc);
            acc = fmaf(xr[tok + 1], wv.y, acc);
            acc = fmaf(xr[tok + 2], wv.z, acc);
            acc = fmaf(xr[tok + 3], wv.w, acc);
            float sv = siluf(acc);
            v[tok][i] = sv;
            g_xc[(size_t)(t0 + tok) * DI + d] = sv;
        }
    }

#pragma unroll
    for (int n = 0; n < 2 * DS + 1; n++) {
        const float* w = Wx + (size_t)n * DI;
        float a0 = 0.f, a1 = 0.f, a2 = 0.f, a3 = 0.f;
#pragma unroll
        for (int i = 0; i < 16; i++) {
            float wv = w[i * 32 + lane];
            a0 = fmaf(v[0][i], wv, a0);
            a1 = fmaf(v[1][i], wv, a1);
            a2 = fmaf(v[2][i], wv, a2);
            a3 = fmaf(v[3][i], wv, a3);
        }
#pragma unroll
        for (int o = 16; o; o >>= 1) {
            a0 += __shfl_xor_sync(NFULL, a0, o);
            a1 += __shfl_xor_sync(NFULL, a1, o);
            a2 += __shfl_xor_sync(NFULL, a2, o);
            a3 += __shfl_xor_sync(NFULL, a3, o);
        }
        if (lane == 0) {
            if (n < DS) {
                g_Bm[(size_t)(t0 + 0) * DS + n] = a0;
                g_Bm[(size_t)(t0 + 1) * DS + n] = a1;
                g_Bm[(size_t)(t0 + 2) * DS + n] = a2;
                g_Bm[(size_t)(t0 + 3) * DS + n] = a3;
            } else if (n < 2 * DS) {
                g_Cm[(size_t)(t0 + 0) * DS + n - DS] = a0;
                g_Cm[(size_t)(t0 + 1) * DS + n - DS] = a1;
                g_Cm[(size_t)(t0 + 2) * DS + n - DS] = a2;
                g_Cm[(size_t)(t0 + 3) * DS + n - DS] = a3;
            } else {
                g_dtraw[t0 + 0] = a0;
                g_dtraw[t0 + 1] = a1;
                g_dtraw[t0 + 2] = a2;
                g_dtraw[t0 + 3] = a3;
            }
        }
    }
}

// w^(s+1) powers via multiply tree
__device__ __forceinline__ void powers16(float w, float* p) {
    p[0] = w;
    p[1] = w * w;
    p[2] = p[1] * w;    p[3]  = p[1] * p[1];
    p[4] = p[3] * w;    p[5]  = p[3] * p[1];
    p[6] = p[3] * p[2]; p[7]  = p[3] * p[3];
    p[8] = p[7] * w;    p[9]  = p[7] * p[1];
    p[10] = p[7] * p[2]; p[11] = p[7] * p[3];
    p[12] = p[7] * p[4]; p[13] = p[7] * p[5];
    p[14] = p[7] * p[6]; p[15] = p[7] * p[7];
}

// ------------------------------------------- scan phase 1: per-chunk scan
__global__ __launch_bounds__(128)
void k_scan1(const float* __restrict__ dw, const float* __restrict__ db) {
    __shared__ float Bs[CL * DS], Cs[CL * DS], dts[CL];
    const int d = blockIdx.x * 128 + threadIdx.x;
    const int c = blockIdx.y, b = blockIdx.z;
    const int tid = threadIdx.x;
    const size_t baseT = (size_t)b * SS + c * CL;

    const float4* Bsrc = reinterpret_cast<const float4*>(g_Bm + baseT * DS);
    const float4* Csrc = reinterpret_cast<const float4*>(g_Cm + baseT * DS);
#pragma unroll
    for (int i = 0; i < CL * DS / 4 / 128; i++) {
        reinterpret_cast<float4*>(Bs)[tid + i * 128] = Bsrc[tid + i * 128];
        reinterpret_cast<float4*>(Cs)[tid + i * 128] = Csrc[tid + i * 128];
    }
    if (tid < CL / 4)
        reinterpret_cast<float4*>(dts)[tid] =
            reinterpret_cast<const float4*>(g_dtraw + baseT)[tid];
    __syncthreads();

    const float dwv = dw[d], dbv = db[d];
    float h[DS];
#pragma unroll
    for (int s = 0; s < DS; s++) h[s] = 0.f;
    float cum = 0.f;

    float xnext = g_xc[baseT * DI + d];
    for (int t = 0; t < CL; t++) {
        float x = xnext;
        if (t + 1 < CL) xnext = g_xc[(baseT + t + 1) * DI + d];
        float xr = dts[t] * dwv + dbv;
        xr = fminf(fmaxf(xr, -30.f), 30.f);
        float e = __expf(xr);
        float w = __frcp_rn(1.f + e);      // exp(-dt)
        float dtv = -__logf(w);            // softplus(xr)
        cum += dtv;
        float u = dtv * x;
        float p[DS];
        powers16(w, p);
        float y = 0.f;
#pragma unroll
        for (int s = 0; s < DS; s++) {
            h[s] = fmaf(h[s], p[s], u * Bs[t * DS + s]);
            y = fmaf(h[s], Cs[t * DS + s], y);
        }
        g_y[(baseT + t) * DI + d] = y;
    }
    g_cumf[((size_t)(b * NCH + c)) * DI + d] = cum;
#pragma unroll
    for (int s = 0; s < DS; s++)
        g_hf[((size_t)(b * NCH + c) * DS + s) * DI + d] = h[s];
}

// ------------------------------------------- scan phase 2: chain chunk states
__global__ void k_scan2() {
    int idx = blockIdx.x * blockDim.x + threadIdx.x;
    if (idx >= BB * DS * DI) return;
    const int d = idx % DI;
    const int s = (idx / DI) % DS;
    const int b = idx / (DI * DS);
    float h = 0.f;
    const float sf = (float)(s + 1);
    for (int c = 0; c < NCH; c++) {
        size_t o = ((size_t)(b * NCH + c) * DS + s) * DI + d;
        g_h0[o] = h;
        float cumt = g_cumf[((size_t)(b * NCH + c)) * DI + d];
        h = fmaf(__expf(-sf * cumt), h, g_hf[o]);
    }
}

// --------------------- scan phase 3: h0 correction + SiLU gating (in place)
__global__ __launch_bounds__(128)
void k_scan3(const float* __restrict__ dw, const float* __restrict__ db) {
    __shared__ float Cs[CL * DS], dts[CL];
    const int c = blockIdx.y;
    const int d = blockIdx.x * 128 + threadIdx.x;
    const int b = blockIdx.z;
    const int tid = threadIdx.x;
    const size_t baseT = (size_t)b * SS + c * CL;

    if (c > 0) {
        const float4* Csrc = reinterpret_cast<const float4*>(g_Cm + baseT * DS);
#pragma unroll
        for (int i = 0; i < CL * DS / 4 / 128; i++)
            reinterpret_cast<float4*>(Cs)[tid + i * 128] = Csrc[tid + i * 128];
        if (tid < CL / 4)
            reinterpret_cast<float4*>(dts)[tid] =
                reinterpret_cast<const float4*>(g_dtraw + baseT)[tid];
        __syncthreads();

        const float dwv = dw[d], dbv = db[d];
        float h0[DS];
#pragma unroll
        for (int s = 0; s < DS; s++)
            h0[s] = g_h0[((size_t)(b * NCH + c) * DS + s) * DI + d];

        float wcum = 1.f;
        for (int t = 0; t < CL; t++) {
            size_t idx = (baseT + t) * DI + d;
            float xr = dts[t] * dwv + dbv;
            xr = fminf(fmaxf(xr, -30.f), 30.f);
            float e = __expf(xr);
            wcum *= __frcp_rn(1.f + e);    // *= exp(-dt_t)
            float p[DS];
            powers16(wcum, p);
            float y = g_y[idx];
#pragma unroll
            for (int s = 0; s < DS; s++)
                y = fmaf(h0[s] * p[s], Cs[t * DS + s], y);
            g_y[idx] = y * siluf(g_z[idx]);
        }
    } else {
        for (int t = 0; t < CL; t++) {
            size_t idx = (baseT + t) * DI + d;
            g_y[idx] = g_y[idx] * siluf(g_z[idx]);
        }
    }
}

// ---------------------------------------------------------- final LN + head
__global__ void k_final(const float* __restrict__ g, const float* __restrict__ b,
                        const float* __restrict__ ow, const float* __restrict__ ob,
                        float* __restrict__ out) {
    int warp = (blockIdx.x * blockDim.x + threadIdx.x) >> 5;
    int lane = threadIdx.x & 31;
    if (warp >= MT) return;
    const float* xr = g_x + (size_t)warp * DM;
    float v[8];
    float s = 0.f;
#pragma unroll
    for (int i = 0; i < 8; i++) { v[i] = xr[i * 32 + lane]; s += v[i]; }
#pragma unroll
    for (int o = 16; o; o >>= 1) s += __shfl_xor_sync(NFULL, s, o);
    float mu = s * (1.f / DM);
    float q = 0.f;
#pragma unroll
    for (int i = 0; i < 8; i++) { float d = v[i] - mu; q += d * d; }
#pragma unroll
    for (int o = 16; o; o >>= 1) q += __shfl_xor_sync(NFULL, q, o);
    float r = rsqrtf(q * (1.f / DM) + EPSV);
    float a0 = 0.f, a1 = 0.f;
#pragma unroll
    for (int i = 0; i < 8; i++) {
        int c = i * 32 + lane;
        float xn = (v[i] - mu) * r * g[c] + b[c];
        a0 += xn * ow[c];
        a1 += xn * ow[DM + c];
    }
#pragma unroll
    for (int o = 16; o; o >>= 1) {
        a0 += __shfl_xor_sync(NFULL, a0, o);
        a1 += __shfl_xor_sync(NFULL, a1, o);
    }
    if (lane == 0) {
        out[(size_t)warp * 2 + 0] = a0 + ob[0];
        out[(size_t)warp * 2 + 1] = a1 + ob[1];
    }
}

// ---------------------------------------------------------------------------
extern "C" void kernel_launch(void* const* d_in, const int* in_sizes, int n_in,
                              void* d_out, int out_size) {
    (void)in_sizes; (void)n_in; (void)out_size;
    const float* z_seq     = (const float*)d_in[0];
    const float* ip_w      = (const float*)d_in[1];
    const float* ip_b      = (const float*)d_in[2];
    const float* norm_g    = (const float*)d_in[3];
    const float* norm_b    = (const float*)d_in[4];
    const float* inproj_w  = (const float*)d_in[5];
    const float* conv_w    = (const float*)d_in[6];
    const float* conv_b    = (const float*)d_in[7];
    const float* xproj_w   = (const float*)d_in[8];
    const float* dt_w      = (const float*)d_in[9];
    const float* dt_b      = (const float*)d_in[10];
    const float* outproj_w = (const float*)d_in[11];
    const float* onorm_g   = (const float*)d_in[12];
    const float* onorm_b   = (const float*)d_in[13];
    const float* op_w      = (const float*)d_in[14];
    const float* op_b      = (const float*)d_in[15];
    float* out = (float*)d_out;

    k_inln<<<MT / 8, 256>>>(z_seq, ip_w, ip_b, norm_g, norm_b);   // launch 1

    for (int l = 0; l < 2; l++) {
        if (l > 0)
            k_ln<<<MT / 8, 256>>>(norm_g + l * DM, norm_b + l * DM);
        k_gemm<0><<<dim3(2 * DI / 128, MT / 128), 256>>>(         // l=0: launch 2
            inproj_w + (size_t)l * 2 * DI * DM);
        k_cxp<<<MT / 4 / 8, 256>>>(conv_w + (size_t)l * DI * 4,   // l=0: launch 3
                                   conv_b + (size_t)l * DI,
                                   xproj_w + (size_t)l * (2 * DS + 1) * DI);
        k_scan1<<<dim3(DI / 128, NCH, BB), 128>>>(dt_w + (size_t)l * DI,  // l=0: launch 4
                                                  dt_b + (size_t)l * DI);
        k_scan2<<<BB * DS * DI / 256, 256>>>();
        k_scan3<<<dim3(DI / 128, NCH, BB), 128>>>(dt_w + (size_t)l * DI,
                                                  dt_b + (size_t)l * DI);
        k_gemm<1><<<dim3(DM / 64, MT / 128), 256>>>(
            outproj_w + (size_t)l * DM * DI);
    }

    k_final<<<MT / 8, 256>>>(onorm_g, onorm_b, op_w, op_b, out);
}

// round 14
// speedup vs baseline: 1.0970x; 1.0379x over previous
#include <cuda_runtime.h>
#include <cstdint>

#define NFULL 0xffffffffu

namespace {
constexpr int BB   = 8;
constexpr int SS   = 4096;
constexpr int DM   = 256;
constexpr int DI   = 512;
constexpr int DS   = 16;
constexpr int MT   = BB * SS;   // 32768 tokens
constexpr int NCH  = 64;        // scan chunks
constexpr int CL   = SS / NCH;  // 64 steps per chunk
constexpr float EPSV = 1e-5f;
}

// ------------------------------------------------------------------ scratch
__device__ __align__(16) float g_x    [MT * DM];   // residual stream
__device__ __align__(16) float g_xn   [MT * DM];   // layernorm output
__device__ __align__(16) float g_xp   [MT * DI];   // inproj half 1
__device__ __align__(16) float g_z    [MT * DI];   // inproj half 2 (gate)
__device__ __align__(16) float g_xc   [MT * DI];   // conv+silu output
__device__ __align__(16) float g_y    [MT * DI];   // scan output (gated by scan3)
__device__ __align__(16) float g_Bm   [MT * DS];
__device__ __align__(16) float g_Cm   [MT * DS];
__device__ __align__(16) float g_dtraw[MT];
__device__ __align__(16) float g_cumf [BB * NCH * DI];       // chunk-final cumsum
__device__ __align__(16) float g_hf   [BB * NCH * DS * DI];
__device__ __align__(16) float g_h0   [BB * NCH * DS * DI];

__device__ __forceinline__ float siluf(float x) {
    return x / (1.f + __expf(-x));
}

// ----------------------------------------- fused inproj + layernorm (layer 0)
__global__ void k_inln(const float* __restrict__ z,
                       const float* __restrict__ w,
                       const float* __restrict__ ipb,
                       const float* __restrict__ g,
                       const float* __restrict__ b) {
    int warp = (blockIdx.x * blockDim.x + threadIdx.x) >> 5;
    int lane = threadIdx.x & 31;
    if (warp >= MT) return;
    float4 zv = *reinterpret_cast<const float4*>(z + (size_t)warp * 4);
    float v[8];
    float s = 0.f;
#pragma unroll
    for (int i = 0; i < 8; i++) {
        int c = i * 32 + lane;
        float4 wv = *reinterpret_cast<const float4*>(w + (size_t)c * 4);
        v[i] = ipb[c] + zv.x * wv.x + zv.y * wv.y + zv.z * wv.z + zv.w * wv.w;
        g_x[(size_t)warp * DM + c] = v[i];
        s += v[i];
    }
#pragma unroll
    for (int o = 16; o; o >>= 1) s += __shfl_xor_sync(NFULL, s, o);
    float mu = s * (1.f / DM);
    float q = 0.f;
#pragma unroll
    for (int i = 0; i < 8; i++) { float d = v[i] - mu; q += d * d; }
#pragma unroll
    for (int o = 16; o; o >>= 1) q += __shfl_xor_sync(NFULL, q, o);
    float r = rsqrtf(q * (1.f / DM) + EPSV);
#pragma unroll
    for (int i = 0; i < 8; i++) {
        int c = i * 32 + lane;
        g_xn[(size_t)warp * DM + c] = (v[i] - mu) * r * g[c] + b[c];
    }
}

// ----------------------------------------------------------------- layernorm
__global__ void k_ln(const float* __restrict__ g, const float* __restrict__ b) {
    int warp = (blockIdx.x * blockDim.x + threadIdx.x) >> 5;
    int lane = threadIdx.x & 31;
    if (warp >= MT) return;
    const float* xr = g_x + (size_t)warp * DM;
    float v[8];
    float s = 0.f;
#pragma unroll
    for (int i = 0; i < 8; i++) { v[i] = xr[i * 32 + lane]; s += v[i]; }
#pragma unroll
    for (int o = 16; o; o >>= 1) s += __shfl_xor_sync(NFULL, s, o);
    float mu = s * (1.f / DM);
    float q = 0.f;
#pragma unroll
    for (int i = 0; i < 8; i++) { float d = v[i] - mu; q += d * d; }
#pragma unroll
    for (int o = 16; o; o >>= 1) q += __shfl_xor_sync(NFULL, q, o);
    float r = rsqrtf(q * (1.f / DM) + EPSV);
    float* out = g_xn + (size_t)warp * DM;
#pragma unroll
    for (int i = 0; i < 8; i++) {
        int c = i * 32 + lane;
        out[c] = (v[i] - mu) * r * g[c] + b[c];
    }
}

// ------------------------------------------------------------------- GEMM v5
// C(MT x N) = A(MT x K) * W^T. BK=16, 256 threads, double-buffered smem,
// one barrier per 16-k chunk, 2 CTAs/SM.
// MODE 0: tile 128x128, A=g_xn (K=256), N=1024 -> g_xp / g_z.
// MODE 1: tile 128x64, A=g_y (gated, K=512), N=256 -> g_x += (residual).
template <int MODE>
__global__ __launch_bounds__(256, 2)
void k_gemm(const float* __restrict__ W) {
    constexpr int K  = (MODE == 0) ? DM : DI;
    constexpr int TN = (MODE == 0) ? 128 : 64;
    constexpr int WN = TN / 2;
    constexpr int BK = 16;
    __shared__ float As[2][BK][128];
    __shared__ float Bs[2][BK][TN];
    const int tid = threadIdx.x;
    const int mBase = blockIdx.y * 128;
    const int nBase = blockIdx.x * TN;
    const int warp = tid >> 5, lane = tid & 31;
    const int wr = warp & 3;
    const int wc = warp >> 2;
    const int lr2 = lane >> 3;
    const int lcx = lane & 7;
    const int lr = tid >> 1;
    const int lc = (tid & 1) * 8;
    const int lrB = (MODE == 0) ? lr : (tid >> 2);
    const int lcB = (MODE == 0) ? lc : ((tid & 3) * 4);

    const float* Aptr = (MODE == 0) ? g_xn : g_y;
    const float* aRow = Aptr + (size_t)(mBase + lr) * K + lc;
    const float* bRow = W + (size_t)(nBase + lrB) * K + lcB;

    float4 pa0, pa1, pb0, pb1;
    auto loadAB = [&](int k0) {
        pa0 = *reinterpret_cast<const float4*>(aRow + k0);
        pa1 = *reinterpret_cast<const float4*>(aRow + k0 + 4);
        pb0 = *reinterpret_cast<const float4*>(bRow + k0);
        if (MODE == 0)
            pb1 = *reinterpret_cast<const float4*>(bRow + k0 + 4);
    };
    auto store = [&](int st) {
        As[st][lc + 0][lr] = pa0.x; As[st][lc + 1][lr] = pa0.y;
        As[st][lc + 2][lr] = pa0.z; As[st][lc + 3][lr] = pa0.w;
        As[st][lc + 4][lr] = pa1.x; As[st][lc + 5][lr] = pa1.y;
        As[st][lc + 6][lr] = pa1.z; As[st][lc + 7][lr] = pa1.w;
        Bs[st][lcB + 0][lrB] = pb0.x; Bs[st][lcB + 1][lrB] = pb0.y;
        Bs[st][lcB + 2][lrB] = pb0.z; Bs[st][lcB + 3][lrB] = pb0.w;
        if (MODE == 0) {
            Bs[st][lcB + 4][lrB] = pb1.x; Bs[st][lcB + 5][lrB] = pb1.y;
            Bs[st][lcB + 6][lrB] = pb1.z; Bs[st][lcB + 7][lrB] = pb1.w;
        }
    };

    constexpr int NJ = (MODE == 0) ? 8 : 4;
    float acc[8][NJ];
#pragma unroll
    for (int i = 0; i < 8; i++)
#pragma unroll
        for (int j = 0; j < NJ; j++) acc[i][j] = 0.f;

    loadAB(0);
    store(0);
    __syncthreads();

    const int aOff0 = wr * 32 + lr2 * 4;
    const int bOff0 = wc * WN + lcx * 4;

    for (int k0 = 0; k0 < K; k0 += BK) {
        const int cur = (k0 >> 4) & 1;
        const bool more = (k0 + BK) < K;
        if (more) loadAB(k0 + BK);
#pragma unroll
        for (int kk = 0; kk < BK; kk++) {
            float4 a0 = *reinterpret_cast<const float4*>(&As[cur][kk][aOff0]);
            float4 a1 = *reinterpret_cast<const float4*>(&As[cur][kk][aOff0 + 16]);
            const float af[8] = {a0.x, a0.y, a0.z, a0.w, a1.x, a1.y, a1.z, a1.w};
            float bf[NJ];
            {
                float4 b0 = *reinterpret_cast<const float4*>(&Bs[cur][kk][bOff0]);
                bf[0] = b0.x; bf[1] = b0.y; bf[2] = b0.z; bf[3] = b0.w;
                if (MODE == 0) {
                    float4 b1 = *reinterpret_cast<const float4*>(&Bs[cur][kk][bOff0 + 32]);
                    bf[4] = b1.x; bf[5] = b1.y; bf[6] = b1.z; bf[7] = b1.w;
                }
            }
#pragma unroll
            for (int i = 0; i < 8; i++)
#pragma unroll
                for (int j = 0; j < NJ; j++)
                    acc[i][j] = fmaf(af[i], bf[j], acc[i][j]);
        }
        if (more) store(cur ^ 1);
        __syncthreads();
    }

#pragma unroll
    for (int i = 0; i < 8; i++) {
        int row = mBase + wr * 32 + (i >> 2) * 16 + lr2 * 4 + (i & 3);
#pragma unroll
        for (int jh = 0; jh < NJ / 4; jh++) {
            int n0 = nBase + wc * WN + jh * 32 + lcx * 4;
            float4 v = make_float4(acc[i][jh * 4], acc[i][jh * 4 + 1],
                                   acc[i][jh * 4 + 2], acc[i][jh * 4 + 3]);
            if (MODE == 0) {
                float* dst = (n0 < DI) ? (g_xp + (size_t)row * DI + n0)
                                       : (g_z  + (size_t)row * DI + n0 - DI);
                *reinterpret_cast<float4*>(dst) = v;
            } else {
                float4* p = reinterpret_cast<float4*>(g_x + (size_t)row * DM + n0);
                float4 o = *p;
                o.x += v.x; o.y += v.y; o.z += v.z; o.w += v.w;
                *p = o;
            }
        }
    }
}

// ---------------------------------- fused depthwise conv + SiLU + xproj GEMV
// v4: one warp handles 4 consecutive tokens (proven R13).
__global__ __launch_bounds__(256)
void k_cxp(const float* __restrict__ cw, const float* __restrict__ cb,
           const float* __restrict__ Wx) {
    const int wid = (blockIdx.x * blockDim.x + threadIdx.x) >> 5;
    const int lane = threadIdx.x & 31;
    const int t0 = wid * 4;
    if (t0 >= MT) return;
    const int tl0 = t0 & (SS - 1);

    float v[4][16];
#pragma unroll
    for (int i = 0; i < 16; i++) {
        const int d = i * 32 + lane;
        float4 wv = *reinterpret_cast<const float4*>(cw + (size_t)d * 4);
        const float cbv = cb[d];
        float xr[7];
#pragma unroll
        for (int k = 0; k < 7; k++) {
            int tt = tl0 - 3 + k;
            xr[k] = (tt >= 0) ? g_xp[(size_t)(t0 - 3 + k) * DI + d] : 0.f;
        }
#pragma unroll
        for (int tok = 0; tok < 4; tok++) {
            float acc = cbv;
            acc = fmaf(xr[tok + 0], wv.x, acc);
            acc = fmaf(xr[tok + 1], wv.y, acc);
            acc = fmaf(xr[tok + 2], wv.z, acc);
            acc = fmaf(xr[tok + 3], wv.w, acc);
            float sv = siluf(acc);
            v[tok][i] = sv;
            g_xc[(size_t)(t0 + tok) * DI + d] = sv;
        }
    }

#pragma unroll
    for (int n = 0; n < 2 * DS + 1; n++) {
        const float* w = Wx + (size_t)n * DI;
        float a0 = 0.f, a1 = 0.f, a2 = 0.f, a3 = 0.f;
#pragma unroll
        for (int i = 0; i < 16; i++) {
            float wv = w[i * 32 + lane];
            a0 = fmaf(v[0][i], wv, a0);
            a1 = fmaf(v[1][i], wv, a1);
            a2 = fmaf(v[2][i], wv, a2);
            a3 = fmaf(v[3][i], wv, a3);
        }
#pragma unroll
        for (int o = 16; o; o >>= 1) {
            a0 += __shfl_xor_sync(NFULL, a0, o);
            a1 += __shfl_xor_sync(NFULL, a1, o);
            a2 += __shfl_xor_sync(NFULL, a2, o);
            a3 += __shfl_xor_sync(NFULL, a3, o);
        }
        if (lane == 0) {
            if (n < DS) {
                g_Bm[(size_t)(t0 + 0) * DS + n] = a0;
                g_Bm[(size_t)(t0 + 1) * DS + n] = a1;
                g_Bm[(size_t)(t0 + 2) * DS + n] = a2;
                g_Bm[(size_t)(t0 + 3) * DS + n] = a3;
            } else if (n < 2 * DS) {
                g_Cm[(size_t)(t0 + 0) * DS + n - DS] = a0;
                g_Cm[(size_t)(t0 + 1) * DS + n - DS] = a1;
                g_Cm[(size_t)(t0 + 2) * DS + n - DS] = a2;
                g_Cm[(size_t)(t0 + 3) * DS + n - DS] = a3;
            } else {
                g_dtraw[t0 + 0] = a0;
                g_dtraw[t0 + 1] = a1;
                g_dtraw[t0 + 2] = a2;
                g_dtraw[t0 + 3] = a3;
            }
        }
    }
}

// w^(s+1) powers via multiply tree
__device__ __forceinline__ void powers16(float w, float* p) {
    p[0] = w;
    p[1] = w * w;
    p[2] = p[1] * w;    p[3]  = p[1] * p[1];
    p[4] = p[3] * w;    p[5]  = p[3] * p[1];
    p[6] = p[3] * p[2]; p[7]  = p[3] * p[3];
    p[8] = p[7] * w;    p[9]  = p[7] * p[1];
    p[10] = p[7] * p[2]; p[11] = p[7] * p[3];
    p[12] = p[7] * p[4]; p[13] = p[7] * p[5];
    p[14] = p[7] * p[6]; p[15] = p[7] * p[7];
}

// ------------------------------------------- scan phase 1: per-chunk scan
__global__ __launch_bounds__(128)
void k_scan1(const float* __restrict__ dw, const float* __restrict__ db) {
    __shared__ float Bs[CL * DS], Cs[CL * DS], dts[CL];
    const int d = blockIdx.x * 128 + threadIdx.x;
    const int c = blockIdx.y, b = blockIdx.z;
    const int tid = threadIdx.x;
    const size_t baseT = (size_t)b * SS + c * CL;

    const float4* Bsrc = reinterpret_cast<const float4*>(g_Bm + baseT * DS);
    const float4* Csrc = reinterpret_cast<const float4*>(g_Cm + baseT * DS);
#pragma unroll
    for (int i = 0; i < CL * DS / 4 / 128; i++) {
        reinterpret_cast<float4*>(Bs)[tid + i * 128] = Bsrc[tid + i * 128];
        reinterpret_cast<float4*>(Cs)[tid + i * 128] = Csrc[tid + i * 128];
    }
    if (tid < CL / 4)
        reinterpret_cast<float4*>(dts)[tid] =
            reinterpret_cast<const float4*>(g_dtraw + baseT)[tid];
    __syncthreads();

    const float dwv = dw[d], dbv = db[d];
    float h[DS];
#pragma unroll
    for (int s = 0; s < DS; s++) h[s] = 0.f;
    float cum = 0.f;

    float xnext = g_xc[baseT * DI + d];
    for (int t = 0; t < CL; t++) {
        float x = xnext;
        if (t + 1 < CL) xnext = g_xc[(baseT + t + 1) * DI + d];
        float xr = dts[t] * dwv + dbv;
        xr = fminf(fmaxf(xr, -30.f), 30.f);
        float e = __expf(xr);
        float w = __frcp_rn(1.f + e);      // exp(-dt)
        float dtv = -__logf(w);            // softplus(xr)
        cum += dtv;
        float u = dtv * x;
        float p[DS];
        powers16(w, p);
        float y = 0.f;
#pragma unroll
        for (int s = 0; s < DS; s++) {
            h[s] = fmaf(h[s], p[s], u * Bs[t * DS + s]);
            y = fmaf(h[s], Cs[t * DS + s], y);
        }
        g_y[(baseT + t) * DI + d] = y;
    }
    g_cumf[((size_t)(b * NCH + c)) * DI + d] = cum;
#pragma unroll
    for (int s = 0; s < DS; s++)
        g_hf[((size_t)(b * NCH + c) * DS + s) * DI + d] = h[s];
}

// ------------------------------------------- scan phase 2: chain chunk states
// software-pipelined: next chunk's hf/cumf loads issued before current step.
__global__ void k_scan2() {
    int idx = blockIdx.x * blockDim.x + threadIdx.x;
    if (idx >= BB * DS * DI) return;
    const int d = idx % DI;
    const int s = (idx / DI) % DS;
    const int b = idx / (DI * DS);
    float h = 0.f;
    const float sf = (float)(s + 1);
    size_t o = ((size_t)(b * NCH) * DS + s) * DI + d;
    size_t oc = ((size_t)(b * NCH)) * DI + d;
    constexpr size_t OSTEP = (size_t)DS * DI;
    float hf = g_hf[o];
    float cf = g_cumf[oc];
    for (int c = 0; c < NCH; c++) {
        float hfn = 0.f, cfn = 0.f;
        if (c + 1 < NCH) {
            hfn = g_hf[o + OSTEP];
            cfn = g_cumf[oc + DI];
        }
        g_h0[o] = h;
        h = fmaf(__expf(-sf * cf), h, hf);
        hf = hfn; cf = cfn;
        o += OSTEP; oc += DI;
    }
}

// --------------------- scan phase 3: h0 correction + SiLU gating (in place)
// software-pipelined y/z prefetch; exp(-cum) recomputed multiplicatively.
__global__ __launch_bounds__(128)
void k_scan3(const float* __restrict__ dw, const float* __restrict__ db) {
    __shared__ float Cs[CL * DS], dts[CL];
    const int c = blockIdx.y;
    const int d = blockIdx.x * 128 + threadIdx.x;
    const int b = blockIdx.z;
    const int tid = threadIdx.x;
    const size_t baseT = (size_t)b * SS + c * CL;

    if (c > 0) {
        const float4* Csrc = reinterpret_cast<const float4*>(g_Cm + baseT * DS);
#pragma unroll
        for (int i = 0; i < CL * DS / 4 / 128; i++)
            reinterpret_cast<float4*>(Cs)[tid + i * 128] = Csrc[tid + i * 128];
        if (tid < CL / 4)
            reinterpret_cast<float4*>(dts)[tid] =
                reinterpret_cast<const float4*>(g_dtraw + baseT)[tid];
        __syncthreads();

        const float dwv = dw[d], dbv = db[d];
        float h0[DS];
#pragma unroll
        for (int s = 0; s < DS; s++)
            h0[s] = g_h0[((size_t)(b * NCH + c) * DS + s) * DI + d];

        float wcum = 1.f;
        size_t idx = baseT * DI + d;
        float ycur = g_y[idx];
        float zcur = g_z[idx];
        for (int t = 0; t < CL; t++) {
            float ynext = 0.f, znext = 0.f;
            if (t + 1 < CL) {
                ynext = g_y[idx + DI];
                znext = g_z[idx + DI];
            }
            float xr = dts[t] * dwv + dbv;
            xr = fminf(fmaxf(xr, -30.f), 30.f);
            float e = __expf(xr);
            wcum *= __frcp_rn(1.f + e);    // *= exp(-dt_t)
            float p[DS];
            powers16(wcum, p);
            float y = ycur;
#pragma unroll
            for (int s = 0; s < DS; s++)
                y = fmaf(h0[s] * p[s], Cs[t * DS + s], y);
            g_y[idx] = y * siluf(zcur);
            ycur = ynext; zcur = znext; idx += DI;
        }
    } else {
        size_t idx = baseT * DI + d;
        float ycur = g_y[idx];
        float zcur = g_z[idx];
        for (int t = 0; t < CL; t++) {
            float ynext = 0.f, znext = 0.f;
            if (t + 1 < CL) {
                ynext = g_y[idx + DI];
                znext = g_z[idx + DI];
            }
            g_y[idx] = ycur * siluf(zcur);
            ycur = ynext; zcur = znext; idx += DI;
        }
    }
}

// ---------------------------------------------------------- final LN + head
__global__ void k_final(const float* __restrict__ g, const float* __restrict__ b,
                        const float* __restrict__ ow, const float* __restrict__ ob,
                        float* __restrict__ out) {
    int warp = (blockIdx.x * blockDim.x + threadIdx.x) >> 5;
    int lane = threadIdx.x & 31;
    if (warp >= MT) return;
    const float* xr = g_x + (size_t)warp * DM;
    float v[8];
    float s = 0.f;
#pragma unroll
    for (int i = 0; i < 8; i++) { v[i] = xr[i * 32 + lane]; s += v[i]; }
#pragma unroll
    for (int o = 16; o; o >>= 1) s += __shfl_xor_sync(NFULL, s, o);
    float mu = s * (1.f / DM);
    float q = 0.f;
#pragma unroll
    for (int i = 0; i < 8; i++) { float d = v[i] - mu; q += d * d; }
#pragma unroll
    for (int o = 16; o; o >>= 1) q += __shfl_xor_sync(NFULL, q, o);
    float r = rsqrtf(q * (1.f / DM) + EPSV);
    float a0 = 0.f, a1 = 0.f;
#pragma unroll
    for (int i = 0; i < 8; i++) {
        int c = i * 32 + lane;
        float xn = (v[i] - mu) * r * g[c] + b[c];
        a0 += xn * ow[c];
        a1 += xn * ow[DM + c];
    }
#pragma unroll
    for (int o = 16; o; o >>= 1) {
        a0 += __shfl_xor_sync(NFULL, a0, o);
        a1 += __shfl_xor_sync(NFULL, a1, o);
    }
    if (lane == 0) {
        out[(size_t)warp * 2 + 0] = a0 + ob[0];
        out[(size_t)warp * 2 + 1] = a1 + ob[1];
    }
}

// ---------------------------------------------------------------------------
extern "C" void kernel_launch(void* const* d_in, const int* in_sizes, int n_in,
                              void* d_out, int out_size) {
    (void)in_sizes; (void)n_in; (void)out_size;
    const float* z_seq     = (const float*)d_in[0];
    const float* ip_w      = (const float*)d_in[1];
    const float* ip_b      = (const float*)d_in[2];
    const float* norm_g    = (const float*)d_in[3];
    const float* norm_b    = (const float*)d_in[4];
    const float* inproj_w  = (const float*)d_in[5];
    const float* conv_w    = (const float*)d_in[6];
    const float* conv_b    = (const float*)d_in[7];
    const float* xproj_w   = (const float*)d_in[8];
    const float* dt_w      = (const float*)d_in[9];
    const float* dt_b      = (const float*)d_in[10];
    const float* outproj_w = (const float*)d_in[11];
    const float* onorm_g   = (const float*)d_in[12];
    const float* onorm_b   = (const float*)d_in[13];
    const float* op_w      = (const float*)d_in[14];
    const float* op_b      = (const float*)d_in[15];
    float* out = (float*)d_out;

    k_inln<<<MT / 8, 256>>>(z_seq, ip_w, ip_b, norm_g, norm_b);   // launch 1

    for (int l = 0; l < 2; l++) {
        if (l > 0)
            k_ln<<<MT / 8, 256>>>(norm_g + l * DM, norm_b + l * DM);
        k_gemm<0><<<dim3(2 * DI / 128, MT / 128), 256>>>(         // l=0: launch 2
            inproj_w + (size_t)l * 2 * DI * DM);
        k_cxp<<<MT / 4 / 8, 256>>>(conv_w + (size_t)l * DI * 4,   // l=0: launch 3
                                   conv_b + (size_t)l * DI,
                                   xproj_w + (size_t)l * (2 * DS + 1) * DI);
        k_scan1<<<dim3(DI / 128, NCH, BB), 128>>>(dt_w + (size_t)l * DI,  // l=0: launch 4
                                                  dt_b + (size_t)l * DI);
        k_scan2<<<BB * DS * DI / 256, 256>>>();
        k_scan3<<<dim3(DI / 128, NCH, BB), 128>>>(dt_w + (size_t)l * DI,
                                                  dt_b + (size_t)l * DI);
        k_gemm<1><<<dim3(DM / 64, MT / 128), 256>>>(
            outproj_w + (size_t)l * DM * DI);
    }

    k_final<<<MT / 8, 256>>>(onorm_g, onorm_b, op_w, op_b, out);
}